// round 8
// baseline (speedup 1.0000x reference)
#include <cuda_runtime.h>
#include <math.h>

#define BC 48          // 16 batch * 3 channels
#define WS 11

typedef unsigned long long u64;

// ---- compile-time gaussian window (sigma=1.5, 11 taps, normalized) ---------
#define GW { 0.00102859f, 0.00759871f, 0.03600077f, 0.10936069f, 0.21300553f, \
             0.26601142f, 0.21300553f, 0.10936069f, 0.03600077f, 0.00759871f, \
             0.00102859f }

// ---------------- f32x2 packed-math helpers (sm_103a) ------------------------
__device__ __forceinline__ u64 pk2(float lo, float hi) {
    u64 r; asm("mov.b64 %0,{%1,%2};" : "=l"(r) : "f"(lo), "f"(hi)); return r;
}
__device__ __forceinline__ void up2(u64 v, float& a, float& b) {
    asm("mov.b64 {%0,%1},%2;" : "=f"(a), "=f"(b) : "l"(v));
}
__device__ __forceinline__ u64 fma2(u64 a, u64 b, u64 c) {
    u64 d; asm("fma.rn.f32x2 %0,%1,%2,%3;" : "=l"(d) : "l"(a), "l"(b), "l"(c)); return d;
}
__device__ __forceinline__ u64 mul2(u64 a, u64 b) {
    u64 d; asm("mul.rn.f32x2 %0,%1,%2;" : "=l"(d) : "l"(a), "l"(b)); return d;
}

// ---------------- device globals (scratch; no runtime allocation) -----------
__device__ double g_cs[5];
__device__ double g_ss[5];
__device__ float g_xa[BC * 256 * 256];
__device__ float g_ya[BC * 256 * 256];
__device__ float g_xb[BC * 128 * 128];
__device__ float g_yb[BC * 128 * 128];

// ---------------- init: zero accumulators -----------------------------------
__global__ void init_kernel() {
    if (threadIdx.x < 5) { g_cs[threadIdx.x] = 0.0; g_ss[threadIdx.x] = 0.0; }
}

// ---------------- fused: separable conv + SSIM stats + 2x2 pool -------------
// Rotated basis u=x+y, v=x-y. s_in packs TWO pixels per float4: (u0,v0,u1,v1).
// Filter packed (u,v) and (u^2,v^2); recover all SSIM terms from A,B,Qa,Qb.
template<int TW, int TH, int NT, int MINB>
__global__ __launch_bounds__(NT, MINB) void ssim_kernel(
    const float* __restrict__ X, const float* __restrict__ Y,
    float* __restrict__ XP, float* __restrict__ YP,
    int H, int W, int level, int do_pool)
{
    constexpr int TIH   = TH + 10, TIW = TW + 10;
    constexpr int NCH   = (TIW + 3) / 4;     // float4 gmem chunks per row
    constexpr int CELLS = 2 * NCH;           // smem float4 cells/row (2 px each)
    constexpr int PIN4  = CELLS + 1;         // odd pitch (float4 units)
    constexpr int PH    = TW + 1;            // h-array pitch (float4 units), odd
    constexpr int RPT   = (TH * TW) / NT;    // output rows/thread in v-pass
    constexpr int NW    = NT / 32;
    constexpr int HU    = TIH * (TW / 2);    // h-pass units (2 cols each)

    __shared__ float4 s_in[TIH * PIN4];      // (u0,v0,u1,v1)
    __shared__ float4 hm  [TIH * PH];        // (Gu,Gv,Gu2,Gv2) per column
    __shared__ double red0[NW], red1[NW];

    const int tid = threadIdx.x;
    const float wreg[WS] = GW;
    u64 wpk[WS];
    #pragma unroll
    for (int k = 0; k < WS; k++) wpk[k] = pk2(wreg[k], wreg[k]);

    const int img  = blockIdx.z;
    const float* Xi = X + (size_t)img * H * W;
    const float* Yi = Y + (size_t)img * H * W;
    const int row0 = blockIdx.y * TH;
    const int col0 = blockIdx.x * TW;

    // ---- load input tile, rotate to (u,v), pack 2 px per float4 ----
    if (row0 + TIH <= H && col0 + 4 * NCH <= W) {
        for (int i = tid; i < TIH * NCH; i += NT) {
            int r = i / NCH, ch = i % NCH;
            const float4 xv = *(const float4*)&Xi[(size_t)(row0 + r) * W + col0 + 4 * ch];
            const float4 yv = *(const float4*)&Yi[(size_t)(row0 + r) * W + col0 + 4 * ch];
            float4* dst = &s_in[r * PIN4 + 2 * ch];
            dst[0] = make_float4(xv.x + yv.x, xv.x - yv.x, xv.y + yv.y, xv.y - yv.y);
            dst[1] = make_float4(xv.z + yv.z, xv.z - yv.z, xv.w + yv.w, xv.w - yv.w);
        }
    } else {
        for (int i = tid; i < TIH * CELLS; i += NT) {
            int r = i / CELLS, cc = i % CELLS;
            int gr = row0 + r;
            int gc0 = col0 + 2 * cc, gc1 = gc0 + 1;
            float x0 = 0.f, y0 = 0.f, x1 = 0.f, y1 = 0.f;
            if (gr < H) {
                if (gc0 < W) { x0 = Xi[(size_t)gr * W + gc0]; y0 = Yi[(size_t)gr * W + gc0]; }
                if (gc1 < W) { x1 = Xi[(size_t)gr * W + gc1]; y1 = Yi[(size_t)gr * W + gc1]; }
            }
            s_in[r * PIN4 + cc] = make_float4(x0 + y0, x0 - y0, x1 + y1, x1 - y1);
        }
    }
    __syncthreads();

    // ---- fused 2x2 avg pool: xp=(Su+Sv)/8, yp=(Su-Sv)/8 ----
    if (do_pool) {
        constexpr int PW = TW / 2, PHT = TH / 2;
        int Ho = H >> 1, Wo = W >> 1;
        for (int i = tid; i < PW * PHT; i += NT) {
            int pr = i / PW, pc = i % PW;
            float4 a = s_in[(2 * pr) * PIN4 + pc];
            float4 b = s_in[(2 * pr + 1) * PIN4 + pc];
            float su = a.x + a.z + b.x + b.z;
            float sv = a.y + a.w + b.y + b.w;
            size_t o = (size_t)img * Ho * Wo + (size_t)((row0 >> 1) + pr) * Wo + (col0 >> 1) + pc;
            XP[o] = 0.125f * (su + sv);
            YP[o] = 0.125f * (su - sv);
        }
    }

    // ---- horizontal pass: 2-column units, row-fastest (conflict-free) ----
    for (int u = tid; u < HU; u += NT) {
        int cgi = u / TIH;                    // column-pair index
        int r   = u - cgi * TIH;
        const float4* pcell = &s_in[r * PIN4 + cgi];  // cells cgi..cgi+5
        u64 m1a = 0, m2a = 0, m1b = 0, m2b = 0;
        #pragma unroll
        for (int cell = 0; cell < 6; cell++) {
            float4 f = pcell[cell];
            u64 p0 = pk2(f.x, f.y), p1 = pk2(f.z, f.w);
            u64 q0 = mul2(p0, p0),  q1 = mul2(p1, p1);
            constexpr int I0 = 0;  // silence unused warn pattern
            (void)I0;
            const int i0 = 2 * cell, i1 = 2 * cell + 1;
            if (i0 < WS)              { m1a = fma2(wpk[i0], p0, m1a); m2a = fma2(wpk[i0], q0, m2a); }
            if (i0 >= 1 && i0 <= WS)  { m1b = fma2(wpk[i0 - 1], p0, m1b); m2b = fma2(wpk[i0 - 1], q0, m2b); }
            if (i1 < WS)              { m1a = fma2(wpk[i1], p1, m1a); m2a = fma2(wpk[i1], q1, m2a); }
            if (i1 >= 1 && i1 <= WS)  { m1b = fma2(wpk[i1 - 1], p1, m1b); m2b = fma2(wpk[i1 - 1], q1, m2b); }
        }
        int o = r * PH + 2 * cgi;
        float A, B, Qa, Qb;
        up2(m1a, A, B); up2(m2a, Qa, Qb);
        hm[o] = make_float4(A, B, Qa, Qb);
        up2(m1b, A, B); up2(m2b, Qa, Qb);
        hm[o + 1] = make_float4(A, B, Qa, Qb);
    }
    __syncthreads();

    // ---- vertical pass + SSIM math (RPT rows per thread) ----
    const float C1 = 0.01f * 0.01f;
    const float C2 = 0.03f * 0.03f;
    const int c  = tid % TW;
    const int r0 = (tid / TW) * RPT;
    const int Hout = H - 10, Wout = W - 10;
    const bool colok = (col0 + c) < Wout;

    u64 a1[RPT], a2[RPT];
    #pragma unroll
    for (int j = 0; j < RPT; j++) { a1[j] = 0; a2[j] = 0; }

    const float4* pv = &hm[r0 * PH + c];
    #pragma unroll
    for (int k = 0; k < RPT + 10; k++) {
        float4 v = pv[k * PH];
        u64 p1 = pk2(v.x, v.y);
        u64 p2 = pk2(v.z, v.w);
        #pragma unroll
        for (int j = 0; j < RPT; j++) {
            int t = k - j;
            if (t >= 0 && t < WS) {
                a1[j] = fma2(wpk[t], p1, a1[j]);
                a2[j] = fma2(wpk[t], p2, a2[j]);
            }
        }
    }

    float cs_sum = 0.f, ss_sum = 0.f;
    #pragma unroll
    for (int j = 0; j < RPT; j++) {
        if (colok && (row0 + r0 + j) < Hout) {
            u64 sq = mul2(a1[j], a1[j]);     // (A^2, B^2)
            float A2, B2, Qa, Qb;
            up2(sq, A2, B2);
            up2(a2[j], Qa, Qb);
            float da = Qa - A2;
            float db = Qb - B2;
            float num  = 0.5f * (da - db) + C2;
            float den  = 0.5f * (da + db) + C2;
            float lnum = 0.5f * (A2 - B2) + C1;
            float lden = 0.5f * (A2 + B2) + C1;
            cs_sum += __fdividef(num, den);
            ss_sum += __fdividef(lnum * num, lden * den);
        }
    }

    // warp + block reduction
    #pragma unroll
    for (int o = 16; o > 0; o >>= 1) {
        cs_sum += __shfl_down_sync(0xffffffffu, cs_sum, o);
        ss_sum += __shfl_down_sync(0xffffffffu, ss_sum, o);
    }
    if ((tid & 31) == 0) { red0[tid >> 5] = cs_sum; red1[tid >> 5] = ss_sum; }
    __syncthreads();
    if (tid == 0) {
        double a = 0.0, b = 0.0;
        #pragma unroll
        for (int w = 0; w < NW; w++) { a += red0[w]; b += red1[w]; }
        atomicAdd(&g_cs[level], a);
        atomicAdd(&g_ss[level], b);
    }
}

// ---------------- final combine ----------------------------------------------
__global__ void finish_kernel(float* __restrict__ out)
{
    if (threadIdx.x != 0) return;
    const double w[5] = {0.0448, 0.2856, 0.3001, 0.2363, 0.1333};
    double ms = 1.0;
    #pragma unroll
    for (int l = 0; l < 5; l++) {
        int Hl = 512 >> l;
        double n  = 48.0 * (double)(Hl - 10) * (double)(Hl - 10);
        double cs = g_cs[l] / n; if (cs < 0.0) cs = 0.0; cs = (cs + 1.0) * 0.5;
        double ss = g_ss[l] / n; if (ss < 0.0) ss = 0.0; ss = (ss + 1.0) * 0.5;
        double v  = (l < 4) ? cs : ss;
        ms *= pow(v, w[l]);
    }
    out[0] = (float)(1.0 - ms);
}

// ---------------- host launch -------------------------------------------------
static inline dim3 conv_grid(int H, int W, int tw, int th) {
    int Hout = H - 10, Wout = W - 10;
    return dim3((Wout + tw - 1) / tw, (Hout + th - 1) / th, BC);
}

extern "C" void kernel_launch(void* const* d_in, const int* in_sizes, int n_in,
                              void* d_out, int out_size)
{
    const float* X0 = (const float*)d_in[0];
    const float* Y0 = (const float*)d_in[1];
    float* out = (float*)d_out;

    float *xa, *ya, *xb, *yb;
    cudaGetSymbolAddress((void**)&xa, g_xa);
    cudaGetSymbolAddress((void**)&ya, g_ya);
    cudaGetSymbolAddress((void**)&xb, g_xb);
    cudaGetSymbolAddress((void**)&yb, g_yb);

    init_kernel<<<1, 32>>>();

    // level 0: 512 -> pool into xa/ya (256)
    ssim_kernel<32, 32, 256, 6><<<conv_grid(512, 512, 32, 32), 256>>>(
        X0, Y0, xa, ya, 512, 512, 0, 1);
    // level 1: 256 -> pool into xb/yb (128)
    ssim_kernel<32, 32, 256, 6><<<conv_grid(256, 256, 32, 32), 256>>>(
        xa, ya, xb, yb, 256, 256, 1, 1);
    // level 2: 128 -> pool into xa/ya (64)
    ssim_kernel<32, 32, 256, 6><<<conv_grid(128, 128, 32, 32), 256>>>(
        xb, yb, xa, ya, 128, 128, 2, 1);
    // level 3: 64 -> pool into xb/yb (32)
    ssim_kernel<16, 16, 128, 8><<<conv_grid(64, 64, 16, 16), 128>>>(
        xa, ya, xb, yb, 64, 64, 3, 1);
    // level 4: 32, no pool
    ssim_kernel<16, 16, 128, 8><<<conv_grid(32, 32, 16, 16), 128>>>(
        xb, yb, nullptr, nullptr, 32, 32, 4, 0);

    finish_kernel<<<1, 32>>>(out);
}

// round 9
// speedup vs baseline: 1.2297x; 1.2297x over previous
#include <cuda_runtime.h>
#include <math.h>

#define BC 48          // 16 batch * 3 channels
#define WS 11

typedef unsigned long long u64;

// ---- compile-time gaussian window (sigma=1.5, 11 taps, normalized) ---------
#define GW { 0.00102859f, 0.00759871f, 0.03600077f, 0.10936069f, 0.21300553f, \
             0.26601142f, 0.21300553f, 0.10936069f, 0.03600077f, 0.00759871f, \
             0.00102859f }

// ---------------- f32x2 packed-math helpers (sm_103a) ------------------------
__device__ __forceinline__ u64 pk2(float lo, float hi) {
    u64 r; asm("mov.b64 %0,{%1,%2};" : "=l"(r) : "f"(lo), "f"(hi)); return r;
}
__device__ __forceinline__ void up2(u64 v, float& a, float& b) {
    asm("mov.b64 {%0,%1},%2;" : "=f"(a), "=f"(b) : "l"(v));
}
__device__ __forceinline__ u64 fma2(u64 a, u64 b, u64 c) {
    u64 d; asm("fma.rn.f32x2 %0,%1,%2,%3;" : "=l"(d) : "l"(a), "l"(b), "l"(c)); return d;
}
__device__ __forceinline__ u64 mul2(u64 a, u64 b) {
    u64 d; asm("mul.rn.f32x2 %0,%1,%2;" : "=l"(d) : "l"(a), "l"(b)); return d;
}

// ---------------- device globals (scratch; no runtime allocation) -----------
__device__ double g_cs[5];
__device__ double g_ss[5];
__device__ float g_xa[BC * 256 * 256];
__device__ float g_ya[BC * 256 * 256];
__device__ float g_xb[BC * 128 * 128];
__device__ float g_yb[BC * 128 * 128];

// ---------------- init: zero accumulators -----------------------------------
__global__ void init_kernel() {
    if (threadIdx.x < 5) { g_cs[threadIdx.x] = 0.0; g_ss[threadIdx.x] = 0.0; }
}

// ---------------- fused: separable conv + SSIM stats + 2x2 pool -------------
// Rotated basis u=x+y, v=x-y, pre-packed as u64 f32x2 pairs in smem.
// Filter packed (u,v) and (u^2,v^2). A=filt(u),B=filt(v),Qa=filt(u2),Qb=filt(v2):
//   2*s12+C2 = (da-db)/2+C2,  s1+s2+C2 = (da+db)/2+C2   (da=Qa-A^2, db=Qb-B^2)
//   2*mu1*mu2+C1 = (A^2-B^2)/2+C1,  mu1^2+mu2^2+C1 = (A^2+B^2)/2+C1
template<int TW, int TH, int NT, int HCW>
__global__ __launch_bounds__(NT) void ssim_kernel(
    const float* __restrict__ X, const float* __restrict__ Y,
    float* __restrict__ XP, float* __restrict__ YP,
    int H, int W, int level, int do_pool)
{
    constexpr int TIH = TH + 10, TIW = TW + 10;
    constexpr int TIW4 = (TIW + 3) & ~3;  // TIW rounded up to float4 multiple
    constexpr int PIN  = (TIW4 + 1) | 1;  // input pitch (u64 units), odd
    constexpr int PH   = TW + 1;          // h-array pitch (ulonglong2 units), odd
    constexpr int CG   = TW / HCW;        // h-pass column groups per row
    constexpr int RPT  = (TH * TW) / NT;  // output rows per thread in v-pass
    constexpr int NW   = NT / 32;

    __shared__ u64        s_in[TIH * PIN];   // packed (u,v)
    __shared__ ulonglong2 hm  [TIH * PH];    // packed {(Gu,Gv),(Gu2,Gv2)}
    __shared__ double red0[NW], red1[NW];

    const int tid = threadIdx.x;
    const float wreg[WS] = GW;
    u64 wpk[WS];
    #pragma unroll
    for (int k = 0; k < WS; k++) wpk[k] = pk2(wreg[k], wreg[k]);

    const int img  = blockIdx.z;
    const float* Xi = X + (size_t)img * H * W;
    const float* Yi = Y + (size_t)img * H * W;
    const int row0 = blockIdx.y * TH;
    const int col0 = blockIdx.x * TW;

    // ---- load input tile, rotate to (u,v) = (x+y, x-y), pack as u64 ----
    if (row0 + TIH <= H && col0 + TIW4 <= W) {
        constexpr int NCH = TIW4 / 4;     // float4 chunks per row
        for (int i = tid; i < TIH * NCH; i += NT) {
            int r = i / NCH, c4 = (i % NCH) * 4;
            const float4 xv = *(const float4*)&Xi[(size_t)(row0 + r) * W + col0 + c4];
            const float4 yv = *(const float4*)&Yi[(size_t)(row0 + r) * W + col0 + c4];
            u64* dst = &s_in[r * PIN + c4];
            dst[0] = pk2(xv.x + yv.x, xv.x - yv.x);
            dst[1] = pk2(xv.y + yv.y, xv.y - yv.y);
            dst[2] = pk2(xv.z + yv.z, xv.z - yv.z);
            dst[3] = pk2(xv.w + yv.w, xv.w - yv.w);
        }
    } else {
        for (int i = tid; i < TIH * TIW; i += NT) {
            int r = i / TIW, c = i % TIW;
            int gr = row0 + r, gc = col0 + c;
            float xv = 0.f, yv = 0.f;
            if (gr < H && gc < W) {
                xv = Xi[(size_t)gr * W + gc];
                yv = Yi[(size_t)gr * W + gc];
            }
            s_in[r * PIN + c] = pk2(xv + yv, xv - yv);
        }
    }
    __syncthreads();

    // ---- fused 2x2 avg pool: x=(u+v)/2, y=(u-v)/2 -> xp=(Su+Sv)/8 ----
    if (do_pool) {
        constexpr int PW = TW / 2, PHT = TH / 2;
        int Ho = H >> 1, Wo = W >> 1;
        for (int i = tid; i < PW * PHT; i += NT) {
            int pr = i / PW, pc = i % PW;
            float au, av, bu, bv, cu, cv, du, dv;
            up2(s_in[(2 * pr) * PIN + 2 * pc],     au, av);
            up2(s_in[(2 * pr) * PIN + 2 * pc + 1], bu, bv);
            up2(s_in[(2 * pr + 1) * PIN + 2 * pc],     cu, cv);
            up2(s_in[(2 * pr + 1) * PIN + 2 * pc + 1], du, dv);
            float su = au + bu + cu + du;
            float sv = av + bv + cv + dv;
            size_t o = (size_t)img * Ho * Wo + (size_t)((row0 >> 1) + pr) * Wo + (col0 >> 1) + pc;
            XP[o] = 0.125f * (su + sv);
            YP[o] = 0.125f * (su - sv);
        }
    }

    // ---- horizontal pass: HCW-column units, row-fastest (conflict-free) ----
    for (int u = tid; u < TIH * CG; u += NT) {
        int cgi = u / TIH;
        int r   = u - cgi * TIH;
        int cg  = cgi * HCW;
        const u64* prow = &s_in[r * PIN + cg];
        u64 m1[HCW], m2[HCW];
        #pragma unroll
        for (int j = 0; j < HCW; j++) { m1[j] = 0; m2[j] = 0; }
        #pragma unroll
        for (int i = 0; i < HCW + 10; i++) {
            u64 vp = prow[i];
            u64 q  = mul2(vp, vp);
            #pragma unroll
            for (int j = 0; j < HCW; j++) {
                int t = i - j;
                if (t >= 0 && t < WS) {
                    m1[j] = fma2(wpk[t], vp, m1[j]);
                    m2[j] = fma2(wpk[t], q,  m2[j]);
                }
            }
        }
        ulonglong2* po = &hm[r * PH + cg];
        #pragma unroll
        for (int j = 0; j < HCW; j++) po[j] = make_ulonglong2(m1[j], m2[j]);
    }
    __syncthreads();

    // ---- vertical pass + SSIM math (RPT rows per thread) ----
    const float C1 = 0.01f * 0.01f;
    const float C2 = 0.03f * 0.03f;
    const int c  = tid % TW;
    const int r0 = (tid / TW) * RPT;
    const int Hout = H - 10, Wout = W - 10;
    const bool colok = (col0 + c) < Wout;

    u64 a1[RPT], a2[RPT];
    #pragma unroll
    for (int j = 0; j < RPT; j++) { a1[j] = 0; a2[j] = 0; }

    const ulonglong2* pv = &hm[r0 * PH + c];
    #pragma unroll
    for (int k = 0; k < RPT + 10; k++) {
        ulonglong2 v = pv[k * PH];
        #pragma unroll
        for (int j = 0; j < RPT; j++) {
            int t = k - j;
            if (t >= 0 && t < WS) {
                a1[j] = fma2(wpk[t], v.x, a1[j]);
                a2[j] = fma2(wpk[t], v.y, a2[j]);
            }
        }
    }

    float cs_sum = 0.f, ss_sum = 0.f;
    #pragma unroll
    for (int j = 0; j < RPT; j++) {
        if (colok && (row0 + r0 + j) < Hout) {
            u64 sq = mul2(a1[j], a1[j]);     // (A^2, B^2)
            float A2, B2, Qa, Qb;
            up2(sq, A2, B2);
            up2(a2[j], Qa, Qb);
            float da = Qa - A2;
            float db = Qb - B2;
            float num  = 0.5f * (da - db) + C2;
            float den  = 0.5f * (da + db) + C2;
            float lnum = 0.5f * (A2 - B2) + C1;
            float lden = 0.5f * (A2 + B2) + C1;
            cs_sum += __fdividef(num, den);
            ss_sum += __fdividef(lnum * num, lden * den);
        }
    }

    // warp + block reduction
    #pragma unroll
    for (int o = 16; o > 0; o >>= 1) {
        cs_sum += __shfl_down_sync(0xffffffffu, cs_sum, o);
        ss_sum += __shfl_down_sync(0xffffffffu, ss_sum, o);
    }
    if ((tid & 31) == 0) { red0[tid >> 5] = cs_sum; red1[tid >> 5] = ss_sum; }
    __syncthreads();
    if (tid == 0) {
        double a = 0.0, b = 0.0;
        #pragma unroll
        for (int w = 0; w < NW; w++) { a += red0[w]; b += red1[w]; }
        atomicAdd(&g_cs[level], a);
        atomicAdd(&g_ss[level], b);
    }
}

// ---------------- final combine ----------------------------------------------
__global__ void finish_kernel(float* __restrict__ out)
{
    if (threadIdx.x != 0) return;
    const double w[5] = {0.0448, 0.2856, 0.3001, 0.2363, 0.1333};
    double ms = 1.0;
    #pragma unroll
    for (int l = 0; l < 5; l++) {
        int Hl = 512 >> l;
        double n  = 48.0 * (double)(Hl - 10) * (double)(Hl - 10);
        double cs = g_cs[l] / n; if (cs < 0.0) cs = 0.0; cs = (cs + 1.0) * 0.5;
        double ss = g_ss[l] / n; if (ss < 0.0) ss = 0.0; ss = (ss + 1.0) * 0.5;
        double v  = (l < 4) ? cs : ss;
        ms *= pow(v, w[l]);
    }
    out[0] = (float)(1.0 - ms);
}

// ---------------- host launch -------------------------------------------------
static inline dim3 conv_grid(int H, int W, int tw, int th) {
    int Hout = H - 10, Wout = W - 10;
    return dim3((Wout + tw - 1) / tw, (Hout + th - 1) / th, BC);
}

extern "C" void kernel_launch(void* const* d_in, const int* in_sizes, int n_in,
                              void* d_out, int out_size)
{
    const float* X0 = (const float*)d_in[0];
    const float* Y0 = (const float*)d_in[1];
    float* out = (float*)d_out;

    float *xa, *ya, *xb, *yb;
    cudaGetSymbolAddress((void**)&xa, g_xa);
    cudaGetSymbolAddress((void**)&ya, g_ya);
    cudaGetSymbolAddress((void**)&xb, g_xb);
    cudaGetSymbolAddress((void**)&yb, g_yb);

    init_kernel<<<1, 32>>>();

    // level 0: 512 -> pool into xa/ya (256)
    ssim_kernel<32, 32, 256, 4><<<conv_grid(512, 512, 32, 32), 256>>>(
        X0, Y0, xa, ya, 512, 512, 0, 1);
    // level 1: 256 -> pool into xb/yb (128)
    ssim_kernel<32, 32, 256, 4><<<conv_grid(256, 256, 32, 32), 256>>>(
        xa, ya, xb, yb, 256, 256, 1, 1);
    // level 2: 128 -> pool into xa/ya (64)
    ssim_kernel<32, 32, 256, 4><<<conv_grid(128, 128, 32, 32), 256>>>(
        xb, yb, xa, ya, 128, 128, 2, 1);
    // level 3: 64 -> pool into xb/yb (32)
    ssim_kernel<16, 16, 128, 4><<<conv_grid(64, 64, 16, 16), 128>>>(
        xa, ya, xb, yb, 64, 64, 3, 1);
    // level 4: 32, no pool
    ssim_kernel<16, 16, 128, 4><<<conv_grid(32, 32, 16, 16), 128>>>(
        xb, yb, nullptr, nullptr, 32, 32, 4, 0);

    finish_kernel<<<1, 32>>>(out);
}